// round 12
// baseline (speedup 1.0000x reference)
#include <cuda_runtime.h>
#include <mma.h>
#include <math.h>
#include <stdint.h>

using namespace nvcuda;

#define KC 64
#define DD 8
#define NC 36
#define KF 64           // padded feature dim
#define RT 64           // rows per tile
#define NBLOCKS 1024
#define NTHREADS 128
#define TPB 2           // tiles per block
#define BTOT 131072

#define LDA 72
#define LDB 72
#define LDD 68

// dynamic smem offsets (bytes)
#define SM_AHI 0                      // 64 x 72 x 4 = 18432
#define SM_ALO 18432
#define SM_BHI 36864
#define SM_BLO 55296
#define SM_D   0                      // alias over AHI (17408 <= 18432)
#define SM_RED 73728                  // 128 floats
#define SM_TOTAL 74496

__device__ __align__(16) float g_Bhi[KC * KF];
__device__ __align__(16) float g_Blo[KC * KF];
__device__ float g_partials[NBLOCKS];
__device__ unsigned g_count = 0;

__device__ __forceinline__ float ex2f(float x) {
    float y; asm("ex2.approx.ftz.f32 %0, %1;" : "=f"(y) : "f"(x)); return y;
}
__device__ __forceinline__ float lg2f(float x) {
    float y; asm("lg2.approx.f32 %0, %1;" : "=f"(y) : "f"(x)); return y;
}

// ---------------------------------------------------------------------------
// Prep: per k compute c_k = [Qij terms, 2*(A^T nw), nw.nw + c2n] (45 vals),
// tf32 hi/lo split, store row-major [k][kf].
// ---------------------------------------------------------------------------
__global__ void prep_kernel(const float* __restrict__ mu,
                            const float* __restrict__ Lc) {
    int k = threadIdx.x;
    if (k >= KC) return;

    float L[DD][DD];
    int m = 0;
#pragma unroll
    for (int i = 0; i < DD; i++)
#pragma unroll
        for (int j = 0; j <= i; j++) L[i][j] = Lc[k * NC + m++];

    float X[DD][DD];
#pragma unroll
    for (int j = 0; j < DD; j++) {
        X[j][j] = 1.0f / L[j][j];
#pragma unroll
        for (int i = j + 1; i < DD; i++) {
            float s = 0.0f;
            for (int t = j; t < i; t++) s = fmaf(L[i][t], X[t][j], s);
            X[i][j] = -s / L[i][i];
        }
    }
    const float SCALE = 0.8493218003f;       // sqrt(0.5/ln2)
    const float C4LOG2PI = 10.6059845179f;   // 4*log2(2pi)

    float A[DD][DD];
#pragma unroll
    for (int i = 0; i < DD; i++)
#pragma unroll
        for (int j = 0; j < DD; j++) A[i][j] = (j <= i) ? X[i][j] * SCALE : 0.0f;

    float nw[DD];
#pragma unroll
    for (int i = 0; i < DD; i++) {
        float acc = 0.0f;
#pragma unroll
        for (int j = 0; j <= i; j++) acc = fmaf(A[i][j], mu[k * DD + j], acc);
        nw[i] = -acc;
    }
    float c2n = C4LOG2PI;
#pragma unroll
    for (int i = 0; i < DD; i++) c2n += lg2f(L[i][i]);

    float c[KF];
    m = 0;
#pragma unroll
    for (int i = 0; i < DD; i++)
#pragma unroll
        for (int j = i; j < DD; j++) {
            float q = 0.0f;
#pragma unroll
            for (int t = 0; t < DD; t++) q = fmaf(A[t][i], A[t][j], q);
            c[m++] = (i == j) ? q : 2.0f * q;
        }
#pragma unroll
    for (int j = 0; j < DD; j++) {
        float l = 0.0f;
#pragma unroll
        for (int t = 0; t < DD; t++) l = fmaf(A[t][j], nw[t], l);
        c[m++] = 2.0f * l;
    }
    {
        float cst = c2n;
#pragma unroll
        for (int i = 0; i < DD; i++) cst = fmaf(nw[i], nw[i], cst);
        c[m++] = cst;
    }
#pragma unroll
    for (; m < KF; m++) c[m] = 0.0f;

#pragma unroll
    for (int i = 0; i < KF; i++) {
        float hi = wmma::__float_to_tf32(c[i]);
        float lo = wmma::__float_to_tf32(c[i] - hi);
        g_Bhi[k * KF + i] = hi;
        g_Blo[k * KF + i] = lo;
    }
}

// ---------------------------------------------------------------------------
// Main: per 64-row tile: phi hi/lo (tf32) in smem -> wmma m16n16k8 GEMM,
// 3 segments -> D smem -> per-row pairwise logsumexp epilogue.
// ---------------------------------------------------------------------------
__global__ void __launch_bounds__(NTHREADS)
main_kernel(const float* __restrict__ pi, const float* __restrict__ target,
            float* __restrict__ out) {
    extern __shared__ __align__(16) char smem[];
    float* Ahi = (float*)(smem + SM_AHI);
    float* Alo = (float*)(smem + SM_ALO);
    float* Bhi = (float*)(smem + SM_BHI);
    float* Blo = (float*)(smem + SM_BLO);
    float* Dsm = (float*)(smem + SM_D);
    float* red = (float*)(smem + SM_RED);

    const int tid = threadIdx.x;
    const int wid = tid >> 5;

    // stage B (row-major [k][KF] -> padded [k][LDB])
    {
        const float4* sh = (const float4*)g_Bhi;
        const float4* sl = (const float4*)g_Blo;
#pragma unroll
        for (int idx = tid; idx < KC * KF / 4; idx += NTHREADS) {
            int row = idx >> 4, c4 = idx & 15;
            *(float4*)(Bhi + row * LDB + c4 * 4) = sh[idx];
            *(float4*)(Blo + row * LDB + c4 * 4) = sl[idx];
        }
    }

    const int rown = tid & 63;     // phi-build row
    const int phalf = tid >> 6;    // which 32 features this thread stores
    const int erow = tid >> 1;     // epilogue row
    const int kh = tid & 1;        // epilogue k-half

    float part = 0.0f;

#pragma unroll 1
    for (int it = 0; it < TPB; it++) {
        const int tile = blockIdx.x + it * NBLOCKS;
        const int row0 = tile * RT;
        __syncthreads();   // B staged (it=0); D reads done (it>0) before A write

        // ---- build phi for my row, store my 32-feature half ----
        {
            float t[DD];
            const float4* tp = (const float4*)(target + (size_t)(row0 + rown) * DD);
            float4 v0 = tp[0], v1 = tp[1];
            t[0] = v0.x; t[1] = v0.y; t[2] = v0.z; t[3] = v0.w;
            t[4] = v1.x; t[5] = v1.y; t[6] = v1.z; t[7] = v1.w;

            float phi[KF];
            int m = 0;
#pragma unroll
            for (int i = 0; i < DD; i++)
#pragma unroll
                for (int j = i; j < DD; j++) phi[m++] = t[i] * t[j];
#pragma unroll
            for (int i = 0; i < DD; i++) phi[m++] = t[i];
            phi[m++] = 1.0f;
#pragma unroll
            for (; m < KF; m++) phi[m] = 0.0f;

            const int c0 = phalf * 32;
            float* ah = Ahi + rown * LDA + c0;
            float* al = Alo + rown * LDA + c0;
#pragma unroll
            for (int c = 0; c < 32; c += 4) {
                float4 h4, l4;
                h4.x = wmma::__float_to_tf32(phi[c0 + c + 0]);
                h4.y = wmma::__float_to_tf32(phi[c0 + c + 1]);
                h4.z = wmma::__float_to_tf32(phi[c0 + c + 2]);
                h4.w = wmma::__float_to_tf32(phi[c0 + c + 3]);
                l4.x = wmma::__float_to_tf32(phi[c0 + c + 0] - h4.x);
                l4.y = wmma::__float_to_tf32(phi[c0 + c + 1] - h4.y);
                l4.z = wmma::__float_to_tf32(phi[c0 + c + 2] - h4.z);
                l4.w = wmma::__float_to_tf32(phi[c0 + c + 3] - h4.w);
                *(float4*)(ah + c) = h4;
                *(float4*)(al + c) = l4;
            }
        }
        __syncthreads();

        // ---- GEMM: warp w -> rows [16w, 16w+16), all 64 cols ----
        wmma::fragment<wmma::accumulator, 16, 16, 8, float> acc[4];
#pragma unroll
        for (int cb = 0; cb < 4; cb++) wmma::fill_fragment(acc[cb], 0.0f);

        const int r0 = wid * 16;
#pragma unroll
        for (int ks = 0; ks < 8; ks++) {
            wmma::fragment<wmma::matrix_a, 16, 16, 8, wmma::precision::tf32,
                           wmma::row_major> ah, al;
            wmma::load_matrix_sync(ah, Ahi + r0 * LDA + ks * 8, LDA);
            wmma::load_matrix_sync(al, Alo + r0 * LDA + ks * 8, LDA);
#pragma unroll
            for (int cb = 0; cb < 4; cb++) {
                wmma::fragment<wmma::matrix_b, 16, 16, 8, wmma::precision::tf32,
                               wmma::col_major> bh, bl;
                wmma::load_matrix_sync(bh, Bhi + cb * 16 * LDB + ks * 8, LDB);
                wmma::load_matrix_sync(bl, Blo + cb * 16 * LDB + ks * 8, LDB);
                wmma::mma_sync(acc[cb], ah, bh, acc[cb]);
                wmma::mma_sync(acc[cb], al, bh, acc[cb]);
                wmma::mma_sync(acc[cb], ah, bl, acc[cb]);
            }
        }
        __syncthreads();   // all A reads done before D store (alias)

#pragma unroll
        for (int cb = 0; cb < 4; cb++)
            wmma::store_matrix_sync(Dsm + r0 * LDD + cb * 16, acc[cb], LDD,
                                    wmma::mem_row_major);
        __syncthreads();

        // ---- epilogue: 2 threads per row, 32 ks each ----
        {
            const float* drow = Dsm + erow * LDD + kh * 32;
            const float* prow = pi + (size_t)(row0 + erow) * KC + kh * 32;
            float mx = -1e30f, sm = 0.0f;
#pragma unroll
            for (int q = 0; q < 8; q++) {
                float4 pv = *(const float4*)(prow + q * 4);
                float4 dv = *(const float4*)(drow + q * 4);
                float w0 = lg2f(pv.x + 1e-10f) - dv.x;
                float w1 = lg2f(pv.y + 1e-10f) - dv.y;
                float w2 = lg2f(pv.z + 1e-10f) - dv.z;
                float w3 = lg2f(pv.w + 1e-10f) - dv.w;
                {
                    float dm = w0 - w1, m01 = fmaxf(w0, w1);
                    float s01 = 1.0f + ex2f(fminf(dm, -dm));
                    float d2 = m01 - mx, e2 = ex2f(fminf(d2, -d2));
                    float shi = fmaf(sm, e2, s01), slo = fmaf(s01, e2, sm);
                    sm = (d2 > 0.0f) ? shi : slo;
                    mx = fmaxf(mx, m01);
                }
                {
                    float dm = w2 - w3, m01 = fmaxf(w2, w3);
                    float s01 = 1.0f + ex2f(fminf(dm, -dm));
                    float d2 = m01 - mx, e2 = ex2f(fminf(d2, -d2));
                    float shi = fmaf(sm, e2, s01), slo = fmaf(s01, e2, sm);
                    sm = (d2 > 0.0f) ? shi : slo;
                    mx = fmaxf(mx, m01);
                }
            }
            // merge the two k-halves of this row (lanes tid, tid^1)
            float mxo = __shfl_xor_sync(0xFFFFFFFFu, mx, 1);
            float smo = __shfl_xor_sync(0xFFFFFFFFu, sm, 1);
            float M = fmaxf(mx, mxo);
            float S = fmaf(sm, ex2f(mx - M), smo * ex2f(mxo - M));
            if (kh == 0) part += M + lg2f(S);
        }
    }

    // block + grid reduction
    red[tid] = part;
    __syncthreads();
#pragma unroll
    for (int s = NTHREADS / 2; s > 0; s >>= 1) {
        if (tid < s) red[tid] += red[tid + s];
        __syncthreads();
    }
    __shared__ bool s_last;
    if (tid == 0) {
        g_partials[blockIdx.x] = red[0];
        __threadfence();
        unsigned done = atomicAdd(&g_count, 1u);
        s_last = (done == NBLOCKS - 1);
    }
    __syncthreads();

    if (s_last) {
        float v = 0.0f;
#pragma unroll
        for (int i = 0; i < NBLOCKS / NTHREADS; i++)
            v += g_partials[tid + i * NTHREADS];
        red[tid] = v;
        __syncthreads();
#pragma unroll
        for (int s = NTHREADS / 2; s > 0; s >>= 1) {
            if (tid < s) red[tid] += red[tid + s];
            __syncthreads();
        }
        if (tid == 0) {
            out[0] = (float)(-0.6931471805599453 * (double)red[0] / (double)BTOT);
            g_count = 0;
        }
    }
}

extern "C" void kernel_launch(void* const* d_in, const int* in_sizes, int n_in,
                              void* d_out, int out_size) {
    const float* pi = (const float*)d_in[0];
    const float* mu = (const float*)d_in[1];
    const float* Lc = (const float*)d_in[2];
    const float* target = (const float*)d_in[3];

    cudaFuncSetAttribute(main_kernel, cudaFuncAttributeMaxDynamicSharedMemorySize,
                         SM_TOTAL);
    prep_kernel<<<1, KC>>>(mu, Lc);
    main_kernel<<<NBLOCKS, NTHREADS, SM_TOTAL>>>(pi, target, (float*)d_out);
}

// round 13
// speedup vs baseline: 2.4050x; 2.4050x over previous
#include <cuda_runtime.h>
#include <math.h>

#define KC 64
#define DD 8
#define NC 36
#define CP 46          // ull entries per k-PAIR: 36 A + 8 nw + 1 c2n + 1 pad
#define NKP (KC / 2)   // 32 k-pairs
#define NBLOCKS 256
#define TX 128
#define TY 2
#define NTHREADS (TX * TY)
#define BTOT 131072

typedef unsigned long long ull;

__device__ float g_partials[NBLOCKS];
__device__ unsigned g_count = 0;

__device__ __forceinline__ float ex2f(float x) {
    float y; asm("ex2.approx.ftz.f32 %0, %1;" : "=f"(y) : "f"(x)); return y;
}
__device__ __forceinline__ float lg2f(float x) {
    float y; asm("lg2.approx.f32 %0, %1;" : "=f"(y) : "f"(x)); return y;
}
__device__ __forceinline__ ull fma2(ull a, ull b, ull c) {
    ull d; asm("fma.rn.f32x2 %0, %1, %2, %3;" : "=l"(d) : "l"(a), "l"(b), "l"(c)); return d;
}
__device__ __forceinline__ ull pack2(float lo, float hi) {
    ull v; asm("mov.b64 %0, {%1, %2};" : "=l"(v) : "f"(lo), "f"(hi)); return v;
}
__device__ __forceinline__ void unpack2(float& lo, float& hi, ull v) {
    asm("mov.b64 {%0, %1}, %2;" : "=f"(lo), "=f"(hi) : "l"(v));
}

// compile-time idx -> LDS.128 half (pairs merge into vec loads, CSE'd)
#define CPAIR(cq, idx) (((idx) & 1) ? (cq)[(idx) >> 1].y : (cq)[(idx) >> 1].x)

// ---------------------------------------------------------------------------
// Single fused kernel. Each block:
//  - threads 0..63 recompute all coefficient sets (fp32 triangular inverse)
//    and write packed k-pair halves straight into smem (no prep kernel)
//  - main loop: f32x2 lanes carry (k_even,k_odd), 4 rows/thread, TY=2 k-split
//  - pairwise online logsumexp; last-block grid reduction
// ---------------------------------------------------------------------------
__global__ void __launch_bounds__(NTHREADS)
main_kernel(const float* __restrict__ pi, const float* __restrict__ mu,
            const float* __restrict__ Lc, const float* __restrict__ target,
            float* __restrict__ out) {
    __shared__ __align__(16) ull sc[NKP * CP];     // 11.5 KB
    __shared__ float s_mx[TX][4], s_sm[TX][4];
    __shared__ float red[NTHREADS];
    __shared__ bool s_last;

    const int tid = threadIdx.x;
    const int half = threadIdx.y;
    const int flat = half * TX + tid;

    // ---- inline prep: thread k (flat<64) computes coefficients for comp k ----
    if (flat < KC) {
        const int k = flat;
        float L[DD][DD];
        int m = 0;
#pragma unroll
        for (int i = 0; i < DD; i++)
#pragma unroll
            for (int j = 0; j <= i; j++)
                L[i][j] = Lc[k * NC + m++];

        float X[DD][DD];
#pragma unroll
        for (int j = 0; j < DD; j++) {
            X[j][j] = 1.0f / L[j][j];
#pragma unroll
            for (int i = j + 1; i < DD; i++) {
                float s = 0.0f;
                for (int t = j; t < i; t++) s = fmaf(L[i][t], X[t][j], s);
                X[i][j] = -s / L[i][i];
            }
        }
        float sumlg2 = 0.0f;
#pragma unroll
        for (int i = 0; i < DD; i++) sumlg2 += lg2f(L[i][i]);

        const float SCALE = 0.8493218003f;        // sqrt(0.5/ln2)
        const float C4LOG2PI = 10.6059845179f;    // 4*log2(2*pi)

        // write my float half of each packed pair: lo half for even k, hi for odd
        float* scf = (float*)sc;
        const int base = (k >> 1) * CP * 2 + (k & 1);
        m = 0;
#pragma unroll
        for (int i = 0; i < DD; i++)
#pragma unroll
            for (int j = 0; j <= i; j++) {
                scf[base + 2 * m] = X[i][j] * SCALE;
                m++;
            }
#pragma unroll
        for (int i = 0; i < DD; i++) {
            float acc = 0.0f;
#pragma unroll
            for (int j = 0; j <= i; j++) acc = fmaf(X[i][j], mu[k * DD + j], acc);
            scf[base + 2 * (36 + i)] = -SCALE * acc;
        }
        scf[base + 2 * 44] = sumlg2 + C4LOG2PI;
        scf[base + 2 * 45] = 0.0f;
    }
    __syncthreads();

    const int b0 = blockIdx.x * (TX * 4) + tid;

    // 4 target rows, each component duplicated into both f32x2 lanes
    ull tpd[4][DD];
#pragma unroll
    for (int r = 0; r < 4; r++) {
        const float4* tp4 = (const float4*)(target + (size_t)(b0 + r * TX) * DD);
        float4 v0 = tp4[0], v1 = tp4[1];
        tpd[r][0] = pack2(v0.x, v0.x); tpd[r][1] = pack2(v0.y, v0.y);
        tpd[r][2] = pack2(v0.z, v0.z); tpd[r][3] = pack2(v0.w, v0.w);
        tpd[r][4] = pack2(v1.x, v1.x); tpd[r][5] = pack2(v1.y, v1.y);
        tpd[r][6] = pack2(v1.z, v1.z); tpd[r][7] = pack2(v1.w, v1.w);
    }

    float mx[4], sm[4];
#pragma unroll
    for (int r = 0; r < 4; r++) { mx[r] = -1e30f; sm[r] = 0.0f; }

    // this half's k range: tiles of 4 k (= 2 k-pairs); 8 tiles per half
#pragma unroll 1
    for (int kt = half * (KC / 8); kt < (half + 1) * (KC / 8); kt++) {
        float p[4][4];
#pragma unroll
        for (int r = 0; r < 4; r++) {
            float4 pv = *((const float4*)(pi + (size_t)(b0 + r * TX) * KC + kt * 4));
            p[r][0] = pv.x; p[r][1] = pv.y; p[r][2] = pv.z; p[r][3] = pv.w;
        }
#pragma unroll
        for (int qq = 0; qq < 2; qq++) {
            const ulonglong2* cq = (const ulonglong2*)(sc + (kt * 2 + qq) * CP);

            ull a[4], macc[4];
            {
                ull nw = CPAIR(cq, 36);
                ull c0 = CPAIR(cq, 0);
                ull c2 = CPAIR(cq, 44);
#pragma unroll
                for (int r = 0; r < 4; r++) a[r] = fma2(c0, tpd[r][0], nw);
#pragma unroll
                for (int r = 0; r < 4; r++) macc[r] = fma2(a[r], a[r], c2);
            }
            int m = 1;
#pragma unroll
            for (int i = 1; i < DD; i++) {
                ull nw = CPAIR(cq, 36 + i);
                ull cj0 = CPAIR(cq, m);
#pragma unroll
                for (int r = 0; r < 4; r++) a[r] = fma2(cj0, tpd[r][0], nw);
#pragma unroll
                for (int j = 1; j <= i; j++) {
                    ull cc = CPAIR(cq, m + j);
#pragma unroll
                    for (int r = 0; r < 4; r++) a[r] = fma2(cc, tpd[r][j], a[r]);
                }
                m += i + 1;
#pragma unroll
                for (int r = 0; r < 4; r++) macc[r] = fma2(a[r], a[r], macc[r]);
            }

#pragma unroll
            for (int r = 0; r < 4; r++) {
                float mm0, mm1;
                unpack2(mm0, mm1, macc[r]);
                // pairwise: combine the 2 k's of this kpair first
                float w0 = lg2f(p[r][qq * 2 + 0] + 1e-10f) - mm0;
                float w1 = lg2f(p[r][qq * 2 + 1] + 1e-10f) - mm1;
                float dm = w0 - w1;
                float e01 = ex2f(fminf(dm, -dm));     // 2^(-|w0-w1|)
                float m01 = fmaxf(w0, w1);
                float s01 = 1.0f + e01;
                // merge (m01, s01) into running state
                float d2 = m01 - mx[r];
                float e2 = ex2f(fminf(d2, -d2));      // 2^(-|d2|)
                float shi = fmaf(sm[r], e2, s01);     // new max path
                float slo = fmaf(s01, e2, sm[r]);     // old max path
                sm[r] = (d2 > 0.0f) ? shi : slo;
                mx[r] = fmaxf(mx[r], m01);
            }
        }
    }

    // merge halves: y=1 publishes, y=0 combines
    if (half == 1) {
#pragma unroll
        for (int r = 0; r < 4; r++) { s_mx[tid][r] = mx[r]; s_sm[tid][r] = sm[r]; }
    }
    __syncthreads();

    float part = 0.0f;
    if (half == 0) {
#pragma unroll
        for (int r = 0; r < 4; r++) {
            float mx1 = s_mx[tid][r], sm1 = s_sm[tid][r];
            float mn = fmaxf(mx[r], mx1);
            float s = fmaf(sm[r], ex2f(mx[r] - mn), sm1 * ex2f(mx1 - mn));
            part += mn + lg2f(s);
        }
    }

    red[flat] = part;
    __syncthreads();
#pragma unroll
    for (int s = NTHREADS / 2; s > 0; s >>= 1) {
        if (flat < s) red[flat] += red[flat + s];
        __syncthreads();
    }
    if (flat == 0) {
        g_partials[blockIdx.x] = red[0];
        __threadfence();
        unsigned done = atomicAdd(&g_count, 1u);
        s_last = (done == NBLOCKS - 1);
    }
    __syncthreads();

    if (s_last) {
        float v = (flat < NBLOCKS) ? g_partials[flat] : 0.0f;
        red[flat] = v;
        __syncthreads();
#pragma unroll
        for (int s = NTHREADS / 2; s > 0; s >>= 1) {
            if (flat < s) red[flat] += red[flat + s];
            __syncthreads();
        }
        if (flat == 0) {
            out[0] = (float)(-0.6931471805599453 * (double)red[0] / (double)BTOT);
            g_count = 0;   // reset for next graph replay
        }
    }
}

extern "C" void kernel_launch(void* const* d_in, const int* in_sizes, int n_in,
                              void* d_out, int out_size) {
    const float* pi = (const float*)d_in[0];
    const float* mu = (const float*)d_in[1];
    const float* Lc = (const float*)d_in[2];
    const float* target = (const float*)d_in[3];

    dim3 blk(TX, TY);
    main_kernel<<<NBLOCKS, blk>>>(pi, mu, Lc, target, (float*)d_out);
}